// round 16
// baseline (speedup 1.0000x reference)
#include <cuda_runtime.h>
#include <cstdint>
#include <cstddef>

// ---------------------------------------------------------------------------
// Problem constants (BiomedCLIP FILIP probe top-k patch selection)
// ---------------------------------------------------------------------------
constexpr int Bb = 512;   // batch
constexpr int Np = 196;   // patches
constexpr int Lt = 256;   // tokens
constexpr int Ed = 768;   // embed dim
constexpr int Pd = 512;   // probe dim
constexpr int Kt = 98;    // top-k
constexpr int OutRows = Kt + 1;   // 99 rows per batch in output

// ---------------------------------------------------------------------------
// Scratch (static device globals; no runtime allocation allowed)
// ---------------------------------------------------------------------------
__device__ float g_pf[(size_t)Bb * Np * Pd];     // raw patch projections
__device__ float g_tf[(size_t)Bb * Lt * Pd];     // compacted token projections
__device__ float g_invn_p[Bb * Np];
__device__ float g_invn_t[Bb * Lt];
__device__ float g_ssp[(size_t)Bb * Np * 4];     // per-row sumsq partials (patch)
__device__ float g_sst[(size_t)Bb * Lt * 4];     // per-row sumsq partials (token)
__device__ float g_part[Bb * 4 * Np];            // per-(b, l-block) partial maxima
__device__ int   g_rowsrc[Bb * OutRows];         // gather source row per output row
__device__ int   g_cidx[Bb * Lt];                // compacted valid-token indices
__device__ int   g_cnt[Bb];                      // valid-token count per batch

typedef unsigned long long ull;

// ---------------------------------------------------------------------------
// Packed fp32x2 FMA helpers (Blackwell FFMA2 — PTX-only)
// ---------------------------------------------------------------------------
__device__ __forceinline__ ull pack2s(float x) {
    ull r; asm("mov.b64 %0, {%1, %1};" : "=l"(r) : "f"(x)); return r;
}
__device__ __forceinline__ void unpack2(ull v, float& lo, float& hi) {
    asm("mov.b64 {%0, %1}, %2;" : "=f"(lo), "=f"(hi) : "l"(v));
}
__device__ __forceinline__ ull ffma2(ull a, ull b, ull c) {
    ull d; asm("fma.rn.f32x2 %0, %1, %2, %3;" : "=l"(d) : "l"(a), "l"(b), "l"(c));
    return d;
}

// ---------------------------------------------------------------------------
// K0: per-batch compaction of valid token indices (attn_mask == 1)
// ---------------------------------------------------------------------------
__global__ __launch_bounds__(256) void compact_tokens(const int* __restrict__ attn)
{
    const int b = blockIdx.x;
    const int tid = threadIdx.x;
    const int lane = tid & 31, w = tid >> 5;
    const int v = attn[b * Lt + tid] != 0;
    const unsigned m = __ballot_sync(0xffffffffu, v);
    __shared__ int wtot[8], wbase[8], s_tot;
    if (lane == 0) wtot[w] = __popc(m);
    __syncthreads();
    if (tid == 0) {
        int s = 0;
#pragma unroll
        for (int i = 0; i < 8; i++) { wbase[i] = s; s += wtot[i]; }
        s_tot = s;
    }
    __syncthreads();
    const int exc = wbase[w] + __popc(m & ((1u << lane) - 1u));
    if (v) g_cidx[b * Lt + exc] = tid;
    if (tid >= s_tot) g_cidx[b * Lt + tid] = 0;   // clamp for tile-padding gathers
    if (tid == 0) g_cnt[b] = s_tot;
}

// ---------------------------------------------------------------------------
// K1: patch projection: C[M,512] = A[M,768] @ W[768,512] + bias (fp32, FFMA2)
// Tile BM=128, BN=128, BK=16. 256 threads, 8x8 outputs/thread (R10 hot loop).
// Epilogue additionally emits per-row sum-of-squares partial for this
// 128-col block (reuses the dead As tile as an 8KB reduction buffer).
// occ target: 2 CTAs/SM (24KB smem/CTA; regs capped at 128 by launch bounds).
// ---------------------------------------------------------------------------
__global__ __launch_bounds__(256, 2) void gemm_proj(
    const float* __restrict__ A, const float* __restrict__ W,
    const float* __restrict__ bias, float* __restrict__ C,
    float* __restrict__ SS)
{
    __shared__ __align__(16) float As[16][128];   // [k][m] (8KB)
    __shared__ __align__(16) float Bs[16][128];   // [k][n] (8KB)

    const int tid = threadIdx.x;
    const int tx = tid & 15;
    const int ty = tid >> 4;
    const int row0 = blockIdx.y * 128;
    const int col0 = blockIdx.x * 128;

    const int aRow0 = tid >> 2,          aC40 = tid & 3;
    const int aRow1 = (tid >> 2) + 64;
    const int wRow0 = tid >> 5,          wC40 = tid & 31;
    const int wRow1 = (tid >> 5) + 8;

    const float* Ab = A + (size_t)row0 * Ed;

    ull acc[8][4];
#pragma unroll
    for (int i = 0; i < 8; i++)
#pragma unroll
        for (int j = 0; j < 4; j++) acc[i][j] = 0ull;

    float4 ra0, ra1, rb0, rb1;
    ra0 = *(const float4*)(Ab + (size_t)aRow0 * Ed + aC40 * 4);
    ra1 = *(const float4*)(Ab + (size_t)aRow1 * Ed + aC40 * 4);
    rb0 = *(const float4*)(W + (size_t)wRow0 * Pd + col0 + wC40 * 4);
    rb1 = *(const float4*)(W + (size_t)wRow1 * Pd + col0 + wC40 * 4);

    for (int kc = 0; kc < Ed / 16; kc++) {
        __syncthreads();
        As[aC40 * 4 + 0][aRow0] = ra0.x; As[aC40 * 4 + 1][aRow0] = ra0.y;
        As[aC40 * 4 + 2][aRow0] = ra0.z; As[aC40 * 4 + 3][aRow0] = ra0.w;
        As[aC40 * 4 + 0][aRow1] = ra1.x; As[aC40 * 4 + 1][aRow1] = ra1.y;
        As[aC40 * 4 + 2][aRow1] = ra1.z; As[aC40 * 4 + 3][aRow1] = ra1.w;
        *(float4*)&Bs[wRow0][wC40 * 4] = rb0;
        *(float4*)&Bs[wRow1][wC40 * 4] = rb1;
        __syncthreads();

        if (kc < Ed / 16 - 1) {
            const int kn = (kc + 1) * 16;
            ra0 = *(const float4*)(Ab + (size_t)aRow0 * Ed + kn + aC40 * 4);
            ra1 = *(const float4*)(Ab + (size_t)aRow1 * Ed + kn + aC40 * 4);
            rb0 = *(const float4*)(W + (size_t)(kn + wRow0) * Pd + col0 + wC40 * 4);
            rb1 = *(const float4*)(W + (size_t)(kn + wRow1) * Pd + col0 + wC40 * 4);
        }

#pragma unroll
        for (int k = 0; k < 16; k++) {
            float4 a0 = *(const float4*)&As[k][ty * 8];
            float4 a1 = *(const float4*)&As[k][ty * 8 + 4];
            ulonglong2 b0 = *(const ulonglong2*)&Bs[k][tx * 8];
            ulonglong2 b1 = *(const ulonglong2*)&Bs[k][tx * 8 + 4];
            ull a2[8];
            a2[0] = pack2s(a0.x); a2[1] = pack2s(a0.y);
            a2[2] = pack2s(a0.z); a2[3] = pack2s(a0.w);
            a2[4] = pack2s(a1.x); a2[5] = pack2s(a1.y);
            a2[6] = pack2s(a1.z); a2[7] = pack2s(a1.w);
#pragma unroll
            for (int i = 0; i < 8; i++) {
                acc[i][0] = ffma2(a2[i], b0.x, acc[i][0]);
                acc[i][1] = ffma2(a2[i], b0.y, acc[i][1]);
                acc[i][2] = ffma2(a2[i], b1.x, acc[i][2]);
                acc[i][3] = ffma2(a2[i], b1.y, acc[i][3]);
            }
        }
    }

    float bv[8];
#pragma unroll
    for (int j = 0; j < 8; j++) bv[j] = bias[col0 + tx * 8 + j];

    __syncthreads();                        // As dead; reuse as reduction buffer
    float* redp = (float*)As;               // [128][16] = 8KB

#pragma unroll
    for (int i = 0; i < 8; i++) {
        const int r = row0 + ty * 8 + i;
        float o[8];
        unpack2(acc[i][0], o[0], o[1]);
        unpack2(acc[i][1], o[2], o[3]);
        unpack2(acc[i][2], o[4], o[5]);
        unpack2(acc[i][3], o[6], o[7]);
#pragma unroll
        for (int j = 0; j < 8; j++) o[j] += bv[j];
        float4 s0 = make_float4(o[0], o[1], o[2], o[3]);
        float4 s1 = make_float4(o[4], o[5], o[6], o[7]);
        float* cp = C + (size_t)r * Pd + col0 + tx * 8;
        *(float4*)cp = s0;
        *(float4*)(cp + 4) = s1;
        float ss = 0.f;
#pragma unroll
        for (int j = 0; j < 8; j++) ss += o[j] * o[j];
        redp[(ty * 8 + i) * 16 + tx] = ss;
    }
    __syncthreads();
    if (tid < 128) {
        float s = redp[tid * 16];
#pragma unroll
        for (int x = 1; x < 16; x++) s += redp[tid * 16 + x];
        SS[(size_t)(row0 + tid) * 4 + blockIdx.x] = s;
    }
}

// ---------------------------------------------------------------------------
// K2: token projection, gather-by-compacted-index variant (tiles past cnt
// skip; R10 hot loop + fused sumsq epilogue), occ target 2 CTAs/SM
// ---------------------------------------------------------------------------
__global__ __launch_bounds__(256, 2) void gemm_proj_gather(
    const float* __restrict__ A, const float* __restrict__ W,
    const float* __restrict__ bias, float* __restrict__ C,
    float* __restrict__ SS)
{
    const int b = blockIdx.y >> 1;
    const int h = blockIdx.y & 1;
    const int cnt = g_cnt[b];
    if (h * 128 >= cnt) return;

    __shared__ __align__(16) float As[16][128];
    __shared__ __align__(16) float Bs[16][128];
    __shared__ int s_idx[128];

    const int tid = threadIdx.x;
    const int tx = tid & 15;
    const int ty = tid >> 4;
    const int row0 = blockIdx.y * 128;           // output slot base = b*256 + h*128
    const int col0 = blockIdx.x * 128;

    if (tid < 128) s_idx[tid] = g_cidx[b * Lt + h * 128 + tid];
    __syncthreads();

    const int aRow0 = tid >> 2,          aC40 = tid & 3;
    const int aRow1 = (tid >> 2) + 64;
    const int wRow0 = tid >> 5,          wC40 = tid & 31;
    const int wRow1 = (tid >> 5) + 8;

    const float* pA0 = A + (size_t)(b * Lt + s_idx[aRow0]) * Ed;
    const float* pA1 = A + (size_t)(b * Lt + s_idx[aRow1]) * Ed;

    ull acc[8][4];
#pragma unroll
    for (int i = 0; i < 8; i++)
#pragma unroll
        for (int j = 0; j < 4; j++) acc[i][j] = 0ull;

    float4 ra0, ra1, rb0, rb1;
    ra0 = *(const float4*)(pA0 + aC40 * 4);
    ra1 = *(const float4*)(pA1 + aC40 * 4);
    rb0 = *(const float4*)(W + (size_t)wRow0 * Pd + col0 + wC40 * 4);
    rb1 = *(const float4*)(W + (size_t)wRow1 * Pd + col0 + wC40 * 4);

    for (int kc = 0; kc < Ed / 16; kc++) {
        __syncthreads();
        As[aC40 * 4 + 0][aRow0] = ra0.x; As[aC40 * 4 + 1][aRow0] = ra0.y;
        As[aC40 * 4 + 2][aRow0] = ra0.z; As[aC40 * 4 + 3][aRow0] = ra0.w;
        As[aC40 * 4 + 0][aRow1] = ra1.x; As[aC40 * 4 + 1][aRow1] = ra1.y;
        As[aC40 * 4 + 2][aRow1] = ra1.z; As[aC40 * 4 + 3][aRow1] = ra1.w;
        *(float4*)&Bs[wRow0][wC40 * 4] = rb0;
        *(float4*)&Bs[wRow1][wC40 * 4] = rb1;
        __syncthreads();

        if (kc < Ed / 16 - 1) {
            const int kn = (kc + 1) * 16;
            ra0 = *(const float4*)(pA0 + kn + aC40 * 4);
            ra1 = *(const float4*)(pA1 + kn + aC40 * 4);
            rb0 = *(const float4*)(W + (size_t)(kn + wRow0) * Pd + col0 + wC40 * 4);
            rb1 = *(const float4*)(W + (size_t)(kn + wRow1) * Pd + col0 + wC40 * 4);
        }

#pragma unroll
        for (int k = 0; k < 16; k++) {
            float4 a0 = *(const float4*)&As[k][ty * 8];
            float4 a1 = *(const float4*)&As[k][ty * 8 + 4];
            ulonglong2 b0 = *(const ulonglong2*)&Bs[k][tx * 8];
            ulonglong2 b1 = *(const ulonglong2*)&Bs[k][tx * 8 + 4];
            ull a2[8];
            a2[0] = pack2s(a0.x); a2[1] = pack2s(a0.y);
            a2[2] = pack2s(a0.z); a2[3] = pack2s(a0.w);
            a2[4] = pack2s(a1.x); a2[5] = pack2s(a1.y);
            a2[6] = pack2s(a1.z); a2[7] = pack2s(a1.w);
#pragma unroll
            for (int i = 0; i < 8; i++) {
                acc[i][0] = ffma2(a2[i], b0.x, acc[i][0]);
                acc[i][1] = ffma2(a2[i], b0.y, acc[i][1]);
                acc[i][2] = ffma2(a2[i], b1.x, acc[i][2]);
                acc[i][3] = ffma2(a2[i], b1.y, acc[i][3]);
            }
        }
    }

    float bv[8];
#pragma unroll
    for (int j = 0; j < 8; j++) bv[j] = bias[col0 + tx * 8 + j];

    __syncthreads();
    float* redp = (float*)As;

#pragma unroll
    for (int i = 0; i < 8; i++) {
        const int r = row0 + ty * 8 + i;
        float o[8];
        unpack2(acc[i][0], o[0], o[1]);
        unpack2(acc[i][1], o[2], o[3]);
        unpack2(acc[i][2], o[4], o[5]);
        unpack2(acc[i][3], o[6], o[7]);
#pragma unroll
        for (int j = 0; j < 8; j++) o[j] += bv[j];
        float4 s0 = make_float4(o[0], o[1], o[2], o[3]);
        float4 s1 = make_float4(o[4], o[5], o[6], o[7]);
        float* cp = C + (size_t)r * Pd + col0 + tx * 8;
        *(float4*)cp = s0;
        *(float4*)(cp + 4) = s1;
        float ss = 0.f;
#pragma unroll
        for (int j = 0; j < 8; j++) ss += o[j] * o[j];
        redp[(ty * 8 + i) * 16 + tx] = ss;
    }
    __syncthreads();
    if (tid < 128) {
        float s = redp[tid * 16];
#pragma unroll
        for (int x = 1; x < 16; x++) s += redp[tid * 16 + x];
        SS[(size_t)(row0 + tid) * 4 + blockIdx.x] = s;
    }
}

// ---------------------------------------------------------------------------
// K3: finish inverse norms from the 4 per-row sumsq partials (tiny)
// ---------------------------------------------------------------------------
__global__ __launch_bounds__(256) void rn_finish()
{
    const int i = blockIdx.x * 256 + threadIdx.x;
    if (i < Bb * Np) {
        const float* p = &g_ssp[(size_t)i * 4];
        float tot = ((p[0] + p[1]) + p[2]) + p[3];
        g_invn_p[i] = 1.0f / fmaxf(sqrtf(tot), 1e-12f);
    } else if (i < Bb * Np + Bb * Lt) {
        const int k = i - Bb * Np;
        const float* p = &g_sst[(size_t)k * 4];
        float tot = ((p[0] + p[1]) + p[2]) + p[3];
        g_invn_t[k] = 1.0f / fmaxf(sqrtf(tot), 1e-12f);
    }
}

// ---------------------------------------------------------------------------
// K4: batched sim + masked-max over compacted tokens (R10 hot loop),
// occ target 2 CTAs/SM (32.7KB smem/CTA -> 65KB of 228KB)
// ---------------------------------------------------------------------------
__global__ __launch_bounds__(256, 2) void simmax()
{
    const int lblk = blockIdx.x;   // 0..3
    const int mblk = blockIdx.y;   // 0..1
    const int b    = blockIdx.z;
    const int tid  = threadIdx.x;
    const int tx = tid & 15;       // cols tx*4 .. +3 (64 cols)
    const int ty = tid >> 4;       // rows ty*8 .. +7 (128 rows)
    const int m0 = mblk * 128;
    const int l0 = lblk * 64;
    const int cnt = g_cnt[b];

    if (l0 >= cnt) {               // inactive l-block: emit sentinels
        if (tid < 128) {
            const int gn = m0 + tid;
            if (gn < Np)
                g_part[((size_t)b * 4 + lblk) * Np + gn] = -3.4e38f;
        }
        return;
    }

    __shared__ __align__(16) float Ps[32][128];   // [k][m] (16KB)
    __shared__ __align__(16) float Ts[32][64];    // [k][l] (8KB)
    __shared__ float red[128][17];                // (8.7KB)

    const float* pf = g_pf + (size_t)b * Np * Pd;
    const float* tf = g_tf + (size_t)b * Lt * Pd;

    ull acc[8][2];
#pragma unroll
    for (int i = 0; i < 8; i++) { acc[i][0] = 0ull; acc[i][1] = 0ull; }

    float4 rp[4], rt[2];
    auto fetch = [&](int kc) {
#pragma unroll
        for (int q = 0; q < 4; q++) {              // Ps: 1024 float4
            int id = tid + 256 * q;
            int row = id >> 3, c4 = id & 7;
            int gm = m0 + row;
            if (gm < Np)
                rp[q] = *(const float4*)(pf + (size_t)gm * Pd + kc * 32 + c4 * 4);
            else
                rp[q] = make_float4(0.f, 0.f, 0.f, 0.f);
        }
#pragma unroll
        for (int q = 0; q < 2; q++) {              // Ts: 512 float4
            int id = tid + 256 * q;
            int row = id >> 3, c4 = id & 7;
            rt[q] = *(const float4*)(tf + (size_t)(l0 + row) * Pd + kc * 32 + c4 * 4);
        }
    };
    fetch(0);

    for (int kc = 0; kc < Pd / 32; kc++) {
        __syncthreads();
#pragma unroll
        for (int q = 0; q < 4; q++) {
            int id = tid + 256 * q;
            int row = id >> 3, c4 = id & 7;
            Ps[c4 * 4 + 0][row] = rp[q].x; Ps[c4 * 4 + 1][row] = rp[q].y;
            Ps[c4 * 4 + 2][row] = rp[q].z; Ps[c4 * 4 + 3][row] = rp[q].w;
        }
#pragma unroll
        for (int q = 0; q < 2; q++) {
            int id = tid + 256 * q;
            int row = id >> 3, c4 = id & 7;
            Ts[c4 * 4 + 0][row] = rt[q].x; Ts[c4 * 4 + 1][row] = rt[q].y;
            Ts[c4 * 4 + 2][row] = rt[q].z; Ts[c4 * 4 + 3][row] = rt[q].w;
        }
        __syncthreads();
        if (kc < Pd / 32 - 1) fetch(kc + 1);

#pragma unroll 8
        for (int k = 0; k < 32; k++) {
            float4 a0 = *(const float4*)&Ps[k][ty * 8];
            float4 a1 = *(const float4*)&Ps[k][ty * 8 + 4];
            ulonglong2 t0 = *(const ulonglong2*)&Ts[k][tx * 4];
            ull a2[8];
            a2[0] = pack2s(a0.x); a2[1] = pack2s(a0.y);
            a2[2] = pack2s(a0.z); a2[3] = pack2s(a0.w);
            a2[4] = pack2s(a1.x); a2[5] = pack2s(a1.y);
            a2[6] = pack2s(a1.z); a2[7] = pack2s(a1.w);
#pragma unroll
            for (int i = 0; i < 8; i++) {
                acc[i][0] = ffma2(a2[i], t0.x, acc[i][0]);
                acc[i][1] = ffma2(a2[i], t0.y, acc[i][1]);
            }
        }
    }

    // epilogue: scale by invn_t, mask by l < cnt, max over this thread's 4 cols
    float it[4]; int mk[4];
#pragma unroll
    for (int c = 0; c < 4; c++) {
        int l = l0 + tx * 4 + c;
        it[c] = g_invn_t[b * Lt + l];
        mk[c] = (l < cnt) ? 1 : 0;
    }
#pragma unroll
    for (int i = 0; i < 8; i++) {
        float v[4];
        unpack2(acc[i][0], v[0], v[1]);
        unpack2(acc[i][1], v[2], v[3]);
        float m = -3.4e38f;
#pragma unroll
        for (int c = 0; c < 4; c++) {
            float cand = mk[c] ? v[c] * it[c] : -3.4e38f;
            m = fmaxf(m, cand);
        }
        red[ty * 8 + i][tx] = m;
    }
    __syncthreads();
    if (tid < 128) {
        float m = red[tid][0];
#pragma unroll
        for (int x = 1; x < 16; x++) m = fmaxf(m, red[tid][x]);
        int gn = m0 + tid;
        if (gn < Np)
            g_part[((size_t)b * 4 + lblk) * Np + gn] = m;
    }
}

// ---------------------------------------------------------------------------
// K5: per-batch exact top-98 by rank counting (tie-break: lower index wins)
// ---------------------------------------------------------------------------
__global__ __launch_bounds__(256) void topk_kernel()
{
    const int b = blockIdx.x;
    const int tid = threadIdx.x;
    __shared__ float s[Np];
    __shared__ int sel[Np];

    if (tid < Np) {
        float m = g_part[((size_t)b * 4 + 0) * Np + tid];
        m = fmaxf(m, g_part[((size_t)b * 4 + 1) * Np + tid]);
        m = fmaxf(m, g_part[((size_t)b * 4 + 2) * Np + tid]);
        m = fmaxf(m, g_part[((size_t)b * 4 + 3) * Np + tid]);
        s[tid] = m * g_invn_p[b * Np + tid];
    }
    __syncthreads();
    if (tid < Np) {
        const float v = s[tid];
        int cnt = 0;
        for (int m = 0; m < Np; m++) {
            float sm = s[m];
            cnt += (sm > v) || (sm == v && m < tid);
        }
        sel[tid] = (cnt < Kt) ? 1 : 0;
    }
    __syncthreads();
    if (tid == 0) {
        const int base = b * OutRows;
        g_rowsrc[base] = b * (Np + 1);          // CLS row
        int pos = 1;
        for (int n = 0; n < Np; n++)
            if (sel[n]) g_rowsrc[base + pos++] = b * (Np + 1) + 1 + n;
    }
}

// ---------------------------------------------------------------------------
// K6: gather rows of state_at_drop into output (bit-exact copies)
// ---------------------------------------------------------------------------
__global__ __launch_bounds__(192) void gather_kernel(const float* __restrict__ state,
                                                     float* __restrict__ out)
{
    const int row = blockIdx.x;                 // 0 .. B*99-1
    const int src = g_rowsrc[row];
    const float4* sp = (const float4*)(state + (size_t)src * Ed);
    float4* op = (float4*)(out + (size_t)row * Ed);
    op[threadIdx.x] = sp[threadIdx.x];          // 192 x float4 = 768 floats
}

// ---------------------------------------------------------------------------
// kernel_launch
// ---------------------------------------------------------------------------
extern "C" void kernel_launch(void* const* d_in, const int* in_sizes, int n_in,
                              void* d_out, int out_size)
{
    const float* patch = (const float*)d_in[0];  // (B, N, E)
    const float* state = (const float*)d_in[1];  // (B, N+1, E)
    const float* token = (const float*)d_in[2];  // (B, L, E)
    const float* W_pp  = (const float*)d_in[3];  // (E, P)
    const float* b_pp  = (const float*)d_in[4];  // (P,)
    const float* W_tp  = (const float*)d_in[5];  // (E, P)
    const float* b_tp  = (const float*)d_in[6];  // (P,)
    const int*   attn  = (const int*)d_in[7];    // (B, L)
    float* out = (float*)d_out;

    void *pf_p, *tf_p, *ssp_p, *sst_p;
    cudaGetSymbolAddress(&pf_p, g_pf);
    cudaGetSymbolAddress(&tf_p, g_tf);
    cudaGetSymbolAddress(&ssp_p, g_ssp);
    cudaGetSymbolAddress(&sst_p, g_sst);

    compact_tokens<<<Bb, 256>>>(attn);
    gemm_proj<<<dim3(Pd / 128, (Bb * Np) / 128), 256>>>(
        patch, W_pp, b_pp, (float*)pf_p, (float*)ssp_p);
    gemm_proj_gather<<<dim3(Pd / 128, (Bb * Lt) / 128), 256>>>(
        token, W_tp, b_tp, (float*)tf_p, (float*)sst_p);
    rn_finish<<<(Bb * Np + Bb * Lt + 255) / 256, 256>>>();
    simmax<<<dim3(4, 2, Bb), 256>>>();
    topk_kernel<<<Bb, 256>>>();
    gather_kernel<<<Bb * OutRows, 192>>>(state, out);
}

// round 17
// speedup vs baseline: 1.0650x; 1.0650x over previous
#include <cuda_runtime.h>
#include <cstdint>
#include <cstddef>

// ---------------------------------------------------------------------------
// Problem constants (BiomedCLIP FILIP probe top-k patch selection)
// ---------------------------------------------------------------------------
constexpr int Bb = 512;   // batch
constexpr int Np = 196;   // patches
constexpr int Lt = 256;   // tokens
constexpr int Ed = 768;   // embed dim
constexpr int Pd = 512;   // probe dim
constexpr int Kt = 98;    // top-k
constexpr int OutRows = Kt + 1;   // 99 rows per batch in output

// ---------------------------------------------------------------------------
// Scratch (static device globals; no runtime allocation allowed)
// ---------------------------------------------------------------------------
__device__ float g_pf[(size_t)Bb * Np * Pd];     // raw patch projections
__device__ float g_tf[(size_t)Bb * Lt * Pd];     // compacted token projections
__device__ float g_invn_p[Bb * Np];
__device__ float g_invn_t[Bb * Lt];
__device__ float g_ssp[(size_t)Bb * Np * 4];     // per-row sumsq partials (patch)
__device__ float g_sst[(size_t)Bb * Lt * 4];     // per-row sumsq partials (token)
__device__ float g_part[Bb * 4 * Np];            // per-(b, l-block) partial maxima
__device__ int   g_rowsrc[Bb * OutRows];         // gather source row per output row
__device__ int   g_cidx[Bb * Lt];                // compacted valid-token indices
__device__ int   g_cnt[Bb];                      // valid-token count per batch

typedef unsigned long long ull;

// ---------------------------------------------------------------------------
// Packed fp32x2 FMA helpers (Blackwell FFMA2 — PTX-only)
// ---------------------------------------------------------------------------
__device__ __forceinline__ ull pack2s(float x) {
    ull r; asm("mov.b64 %0, {%1, %1};" : "=l"(r) : "f"(x)); return r;
}
__device__ __forceinline__ void unpack2(ull v, float& lo, float& hi) {
    asm("mov.b64 {%0, %1}, %2;" : "=f"(lo), "=f"(hi) : "l"(v));
}
__device__ __forceinline__ ull ffma2(ull a, ull b, ull c) {
    ull d; asm("fma.rn.f32x2 %0, %1, %2, %3;" : "=l"(d) : "l"(a), "l"(b), "l"(c));
    return d;
}

// ---------------------------------------------------------------------------
// K0: per-batch compaction of valid token indices (attn_mask == 1)
// ---------------------------------------------------------------------------
__global__ __launch_bounds__(256) void compact_tokens(const int* __restrict__ attn)
{
    const int b = blockIdx.x;
    const int tid = threadIdx.x;
    const int lane = tid & 31, w = tid >> 5;
    const int v = attn[b * Lt + tid] != 0;
    const unsigned m = __ballot_sync(0xffffffffu, v);
    __shared__ int wtot[8], wbase[8], s_tot;
    if (lane == 0) wtot[w] = __popc(m);
    __syncthreads();
    if (tid == 0) {
        int s = 0;
#pragma unroll
        for (int i = 0; i < 8; i++) { wbase[i] = s; s += wtot[i]; }
        s_tot = s;
    }
    __syncthreads();
    const int exc = wbase[w] + __popc(m & ((1u << lane) - 1u));
    if (v) g_cidx[b * Lt + exc] = tid;
    if (tid >= s_tot) g_cidx[b * Lt + tid] = 0;   // clamp for tile-padding gathers
    if (tid == 0) g_cnt[b] = s_tot;
}

// ---------------------------------------------------------------------------
// K1: patch projection: C[M,512] = A[M,768] @ W[768,512] + bias (fp32, FFMA2)
// Tile BM=128, BN=128, BK=16, DOUBLE-BUFFERED (one sync per chunk).
// 256 threads, 8x8 outputs/thread. Epilogue emits per-row sumsq partials
// (reuses the dead As storage as the reduction buffer).
// smem: As 2x8KB + Bs 2x8KB = 32KB.
// ---------------------------------------------------------------------------
__global__ __launch_bounds__(256) void gemm_proj(
    const float* __restrict__ A, const float* __restrict__ W,
    const float* __restrict__ bias, float* __restrict__ C,
    float* __restrict__ SS)
{
    __shared__ __align__(16) float As[2][16][128];   // 16KB
    __shared__ __align__(16) float Bs[2][16][128];   // 16KB

    const int tid = threadIdx.x;
    const int tx = tid & 15;
    const int ty = tid >> 4;
    const int row0 = blockIdx.y * 128;
    const int col0 = blockIdx.x * 128;

    const int aRow0 = tid >> 2,          aC40 = tid & 3;
    const int aRow1 = (tid >> 2) + 64;
    const int wRow0 = tid >> 5,          wC40 = tid & 31;
    const int wRow1 = (tid >> 5) + 8;

    const float* Ab = A + (size_t)row0 * Ed;
    constexpr int NCH = Ed / 16;   // 48

    ull acc[8][4];
#pragma unroll
    for (int i = 0; i < 8; i++)
#pragma unroll
        for (int j = 0; j < 4; j++) acc[i][j] = 0ull;

    float4 ra0, ra1, rb0, rb1;

    // prologue: chunk 0 -> buf 0
    ra0 = *(const float4*)(Ab + (size_t)aRow0 * Ed + aC40 * 4);
    ra1 = *(const float4*)(Ab + (size_t)aRow1 * Ed + aC40 * 4);
    rb0 = *(const float4*)(W + (size_t)wRow0 * Pd + col0 + wC40 * 4);
    rb1 = *(const float4*)(W + (size_t)wRow1 * Pd + col0 + wC40 * 4);
    As[0][aC40 * 4 + 0][aRow0] = ra0.x; As[0][aC40 * 4 + 1][aRow0] = ra0.y;
    As[0][aC40 * 4 + 2][aRow0] = ra0.z; As[0][aC40 * 4 + 3][aRow0] = ra0.w;
    As[0][aC40 * 4 + 0][aRow1] = ra1.x; As[0][aC40 * 4 + 1][aRow1] = ra1.y;
    As[0][aC40 * 4 + 2][aRow1] = ra1.z; As[0][aC40 * 4 + 3][aRow1] = ra1.w;
    *(float4*)&Bs[0][wRow0][wC40 * 4] = rb0;
    *(float4*)&Bs[0][wRow1][wC40 * 4] = rb1;
    __syncthreads();
    // prefetch chunk 1
    ra0 = *(const float4*)(Ab + (size_t)aRow0 * Ed + 16 + aC40 * 4);
    ra1 = *(const float4*)(Ab + (size_t)aRow1 * Ed + 16 + aC40 * 4);
    rb0 = *(const float4*)(W + (size_t)(16 + wRow0) * Pd + col0 + wC40 * 4);
    rb1 = *(const float4*)(W + (size_t)(16 + wRow1) * Pd + col0 + wC40 * 4);

    for (int kc = 0; kc < NCH; kc++) {
        const int p = kc & 1;

#pragma unroll
        for (int k = 0; k < 16; k++) {
            float4 a0 = *(const float4*)&As[p][k][ty * 8];
            float4 a1 = *(const float4*)&As[p][k][ty * 8 + 4];
            ulonglong2 b0 = *(const ulonglong2*)&Bs[p][k][tx * 8];
            ulonglong2 b1 = *(const ulonglong2*)&Bs[p][k][tx * 8 + 4];
            ull a2[8];
            a2[0] = pack2s(a0.x); a2[1] = pack2s(a0.y);
            a2[2] = pack2s(a0.z); a2[3] = pack2s(a0.w);
            a2[4] = pack2s(a1.x); a2[5] = pack2s(a1.y);
            a2[6] = pack2s(a1.z); a2[7] = pack2s(a1.w);
#pragma unroll
            for (int i = 0; i < 8; i++) {
                acc[i][0] = ffma2(a2[i], b0.x, acc[i][0]);
                acc[i][1] = ffma2(a2[i], b0.y, acc[i][1]);
                acc[i][2] = ffma2(a2[i], b1.x, acc[i][2]);
                acc[i][3] = ffma2(a2[i], b1.y, acc[i][3]);
            }
        }

        if (kc + 1 < NCH) {
            const int q = (kc + 1) & 1;
            As[q][aC40 * 4 + 0][aRow0] = ra0.x; As[q][aC40 * 4 + 1][aRow0] = ra0.y;
            As[q][aC40 * 4 + 2][aRow0] = ra0.z; As[q][aC40 * 4 + 3][aRow0] = ra0.w;
            As[q][aC40 * 4 + 0][aRow1] = ra1.x; As[q][aC40 * 4 + 1][aRow1] = ra1.y;
            As[q][aC40 * 4 + 2][aRow1] = ra1.z; As[q][aC40 * 4 + 3][aRow1] = ra1.w;
            *(float4*)&Bs[q][wRow0][wC40 * 4] = rb0;
            *(float4*)&Bs[q][wRow1][wC40 * 4] = rb1;
            __syncthreads();
            if (kc + 2 < NCH) {
                const int kn = (kc + 2) * 16;
                ra0 = *(const float4*)(Ab + (size_t)aRow0 * Ed + kn + aC40 * 4);
                ra1 = *(const float4*)(Ab + (size_t)aRow1 * Ed + kn + aC40 * 4);
                rb0 = *(const float4*)(W + (size_t)(kn + wRow0) * Pd + col0 + wC40 * 4);
                rb1 = *(const float4*)(W + (size_t)(kn + wRow1) * Pd + col0 + wC40 * 4);
            }
        }
    }

    float bv[8];
#pragma unroll
    for (int j = 0; j < 8; j++) bv[j] = bias[col0 + tx * 8 + j];

    __syncthreads();                        // tiles dead; reuse As as red buffer
    float* redp = (float*)As;               // [128][16] = 8KB (within As[0])

#pragma unroll
    for (int i = 0; i < 8; i++) {
        const int r = row0 + ty * 8 + i;
        float o[8];
        unpack2(acc[i][0], o[0], o[1]);
        unpack2(acc[i][1], o[2], o[3]);
        unpack2(acc[i][2], o[4], o[5]);
        unpack2(acc[i][3], o[6], o[7]);
#pragma unroll
        for (int j = 0; j < 8; j++) o[j] += bv[j];
        float4 s0 = make_float4(o[0], o[1], o[2], o[3]);
        float4 s1 = make_float4(o[4], o[5], o[6], o[7]);
        float* cp = C + (size_t)r * Pd + col0 + tx * 8;
        *(float4*)cp = s0;
        *(float4*)(cp + 4) = s1;
        float ss = 0.f;
#pragma unroll
        for (int j = 0; j < 8; j++) ss += o[j] * o[j];
        redp[(ty * 8 + i) * 16 + tx] = ss;
    }
    __syncthreads();
    if (tid < 128) {
        float s = redp[tid * 16];
#pragma unroll
        for (int x = 1; x < 16; x++) s += redp[tid * 16 + x];
        SS[(size_t)(row0 + tid) * 4 + blockIdx.x] = s;
    }
}

// ---------------------------------------------------------------------------
// K2: token projection, gather-by-compacted-index variant (tiles past cnt
// skip), double-buffered like K1.
// ---------------------------------------------------------------------------
__global__ __launch_bounds__(256) void gemm_proj_gather(
    const float* __restrict__ A, const float* __restrict__ W,
    const float* __restrict__ bias, float* __restrict__ C,
    float* __restrict__ SS)
{
    const int b = blockIdx.y >> 1;
    const int h = blockIdx.y & 1;
    const int cnt = g_cnt[b];
    if (h * 128 >= cnt) return;

    __shared__ __align__(16) float As[2][16][128];
    __shared__ __align__(16) float Bs[2][16][128];
    __shared__ int s_idx[128];

    const int tid = threadIdx.x;
    const int tx = tid & 15;
    const int ty = tid >> 4;
    const int row0 = blockIdx.y * 128;           // output slot base = b*256 + h*128
    const int col0 = blockIdx.x * 128;

    if (tid < 128) s_idx[tid] = g_cidx[b * Lt + h * 128 + tid];
    __syncthreads();

    const int aRow0 = tid >> 2,          aC40 = tid & 3;
    const int aRow1 = (tid >> 2) + 64;
    const int wRow0 = tid >> 5,          wC40 = tid & 31;
    const int wRow1 = (tid >> 5) + 8;

    const float* pA0 = A + (size_t)(b * Lt + s_idx[aRow0]) * Ed;
    const float* pA1 = A + (size_t)(b * Lt + s_idx[aRow1]) * Ed;
    constexpr int NCH = Ed / 16;   // 48

    ull acc[8][4];
#pragma unroll
    for (int i = 0; i < 8; i++)
#pragma unroll
        for (int j = 0; j < 4; j++) acc[i][j] = 0ull;

    float4 ra0, ra1, rb0, rb1;

    // prologue: chunk 0 -> buf 0
    ra0 = *(const float4*)(pA0 + aC40 * 4);
    ra1 = *(const float4*)(pA1 + aC40 * 4);
    rb0 = *(const float4*)(W + (size_t)wRow0 * Pd + col0 + wC40 * 4);
    rb1 = *(const float4*)(W + (size_t)wRow1 * Pd + col0 + wC40 * 4);
    As[0][aC40 * 4 + 0][aRow0] = ra0.x; As[0][aC40 * 4 + 1][aRow0] = ra0.y;
    As[0][aC40 * 4 + 2][aRow0] = ra0.z; As[0][aC40 * 4 + 3][aRow0] = ra0.w;
    As[0][aC40 * 4 + 0][aRow1] = ra1.x; As[0][aC40 * 4 + 1][aRow1] = ra1.y;
    As[0][aC40 * 4 + 2][aRow1] = ra1.z; As[0][aC40 * 4 + 3][aRow1] = ra1.w;
    *(float4*)&Bs[0][wRow0][wC40 * 4] = rb0;
    *(float4*)&Bs[0][wRow1][wC40 * 4] = rb1;
    __syncthreads();
    ra0 = *(const float4*)(pA0 + 16 + aC40 * 4);
    ra1 = *(const float4*)(pA1 + 16 + aC40 * 4);
    rb0 = *(const float4*)(W + (size_t)(16 + wRow0) * Pd + col0 + wC40 * 4);
    rb1 = *(const float4*)(W + (size_t)(16 + wRow1) * Pd + col0 + wC40 * 4);

    for (int kc = 0; kc < NCH; kc++) {
        const int p = kc & 1;

#pragma unroll
        for (int k = 0; k < 16; k++) {
            float4 a0 = *(const float4*)&As[p][k][ty * 8];
            float4 a1 = *(const float4*)&As[p][k][ty * 8 + 4];
            ulonglong2 b0 = *(const ulonglong2*)&Bs[p][k][tx * 8];
            ulonglong2 b1 = *(const ulonglong2*)&Bs[p][k][tx * 8 + 4];
            ull a2[8];
            a2[0] = pack2s(a0.x); a2[1] = pack2s(a0.y);
            a2[2] = pack2s(a0.z); a2[3] = pack2s(a0.w);
            a2[4] = pack2s(a1.x); a2[5] = pack2s(a1.y);
            a2[6] = pack2s(a1.z); a2[7] = pack2s(a1.w);
#pragma unroll
            for (int i = 0; i < 8; i++) {
                acc[i][0] = ffma2(a2[i], b0.x, acc[i][0]);
                acc[i][1] = ffma2(a2[i], b0.y, acc[i][1]);
                acc[i][2] = ffma2(a2[i], b1.x, acc[i][2]);
                acc[i][3] = ffma2(a2[i], b1.y, acc[i][3]);
            }
        }

        if (kc + 1 < NCH) {
            const int q = (kc + 1) & 1;
            As[q][aC40 * 4 + 0][aRow0] = ra0.x; As[q][aC40 * 4 + 1][aRow0] = ra0.y;
            As[q][aC40 * 4 + 2][aRow0] = ra0.z; As[q][aC40 * 4 + 3][aRow0] = ra0.w;
            As[q][aC40 * 4 + 0][aRow1] = ra1.x; As[q][aC40 * 4 + 1][aRow1] = ra1.y;
            As[q][aC40 * 4 + 2][aRow1] = ra1.z; As[q][aC40 * 4 + 3][aRow1] = ra1.w;
            *(float4*)&Bs[q][wRow0][wC40 * 4] = rb0;
            *(float4*)&Bs[q][wRow1][wC40 * 4] = rb1;
            __syncthreads();
            if (kc + 2 < NCH) {
                const int kn = (kc + 2) * 16;
                ra0 = *(const float4*)(pA0 + kn + aC40 * 4);
                ra1 = *(const float4*)(pA1 + kn + aC40 * 4);
                rb0 = *(const float4*)(W + (size_t)(kn + wRow0) * Pd + col0 + wC40 * 4);
                rb1 = *(const float4*)(W + (size_t)(kn + wRow1) * Pd + col0 + wC40 * 4);
            }
        }
    }

    float bv[8];
#pragma unroll
    for (int j = 0; j < 8; j++) bv[j] = bias[col0 + tx * 8 + j];

    __syncthreads();
    float* redp = (float*)As;

#pragma unroll
    for (int i = 0; i < 8; i++) {
        const int r = row0 + ty * 8 + i;
        float o[8];
        unpack2(acc[i][0], o[0], o[1]);
        unpack2(acc[i][1], o[2], o[3]);
        unpack2(acc[i][2], o[4], o[5]);
        unpack2(acc[i][3], o[6], o[7]);
#pragma unroll
        for (int j = 0; j < 8; j++) o[j] += bv[j];
        float4 s0 = make_float4(o[0], o[1], o[2], o[3]);
        float4 s1 = make_float4(o[4], o[5], o[6], o[7]);
        float* cp = C + (size_t)r * Pd + col0 + tx * 8;
        *(float4*)cp = s0;
        *(float4*)(cp + 4) = s1;
        float ss = 0.f;
#pragma unroll
        for (int j = 0; j < 8; j++) ss += o[j] * o[j];
        redp[(ty * 8 + i) * 16 + tx] = ss;
    }
    __syncthreads();
    if (tid < 128) {
        float s = redp[tid * 16];
#pragma unroll
        for (int x = 1; x < 16; x++) s += redp[tid * 16 + x];
        SS[(size_t)(row0 + tid) * 4 + blockIdx.x] = s;
    }
}

// ---------------------------------------------------------------------------
// K3: finish inverse norms from the 4 per-row sumsq partials (tiny)
// ---------------------------------------------------------------------------
__global__ __launch_bounds__(256) void rn_finish()
{
    const int i = blockIdx.x * 256 + threadIdx.x;
    if (i < Bb * Np) {
        const float* p = &g_ssp[(size_t)i * 4];
        float tot = ((p[0] + p[1]) + p[2]) + p[3];
        g_invn_p[i] = 1.0f / fmaxf(sqrtf(tot), 1e-12f);
    } else if (i < Bb * Np + Bb * Lt) {
        const int k = i - Bb * Np;
        const float* p = &g_sst[(size_t)k * 4];
        float tot = ((p[0] + p[1]) + p[2]) + p[3];
        g_invn_t[k] = 1.0f / fmaxf(sqrtf(tot), 1e-12f);
    }
}

// ---------------------------------------------------------------------------
// K4: batched sim + masked-max over compacted tokens (R15 form, unchanged)
// ---------------------------------------------------------------------------
__global__ __launch_bounds__(256) void simmax()
{
    const int lblk = blockIdx.x;   // 0..3
    const int mblk = blockIdx.y;   // 0..1
    const int b    = blockIdx.z;
    const int tid  = threadIdx.x;
    const int tx = tid & 15;       // cols tx*4 .. +3 (64 cols)
    const int ty = tid >> 4;       // rows ty*8 .. +7 (128 rows)
    const int m0 = mblk * 128;
    const int l0 = lblk * 64;
    const int cnt = g_cnt[b];

    if (l0 >= cnt) {               // inactive l-block: emit sentinels
        if (tid < 128) {
            const int gn = m0 + tid;
            if (gn < Np)
                g_part[((size_t)b * 4 + lblk) * Np + gn] = -3.4e38f;
        }
        return;
    }

    __shared__ __align__(16) float Ps[32][128];   // [k][m] (16KB)
    __shared__ __align__(16) float Ts[32][64];    // [k][l] (8KB)
    __shared__ float red[128][17];                // (8.7KB)

    const float* pf = g_pf + (size_t)b * Np * Pd;
    const float* tf = g_tf + (size_t)b * Lt * Pd;

    ull acc[8][2];
#pragma unroll
    for (int i = 0; i < 8; i++) { acc[i][0] = 0ull; acc[i][1] = 0ull; }

    float4 rp[4], rt[2];
    auto fetch = [&](int kc) {
#pragma unroll
        for (int q = 0; q < 4; q++) {              // Ps: 1024 float4
            int id = tid + 256 * q;
            int row = id >> 3, c4 = id & 7;
            int gm = m0 + row;
            if (gm < Np)
                rp[q] = *(const float4*)(pf + (size_t)gm * Pd + kc * 32 + c4 * 4);
            else
                rp[q] = make_float4(0.f, 0.f, 0.f, 0.f);
        }
#pragma unroll
        for (int q = 0; q < 2; q++) {              // Ts: 512 float4
            int id = tid + 256 * q;
            int row = id >> 3, c4 = id & 7;
            rt[q] = *(const float4*)(tf + (size_t)(l0 + row) * Pd + kc * 32 + c4 * 4);
        }
    };
    fetch(0);

    for (int kc = 0; kc < Pd / 32; kc++) {
        __syncthreads();
#pragma unroll
        for (int q = 0; q < 4; q++) {
            int id = tid + 256 * q;
            int row = id >> 3, c4 = id & 7;
            Ps[c4 * 4 + 0][row] = rp[q].x; Ps[c4 * 4 + 1][row] = rp[q].y;
            Ps[c4 * 4 + 2][row] = rp[q].z; Ps[c4 * 4 + 3][row] = rp[q].w;
        }
#pragma unroll
        for (int q = 0; q < 2; q++) {
            int id = tid + 256 * q;
            int row = id >> 3, c4 = id & 7;
            Ts[c4 * 4 + 0][row] = rt[q].x; Ts[c4 * 4 + 1][row] = rt[q].y;
            Ts[c4 * 4 + 2][row] = rt[q].z; Ts[c4 * 4 + 3][row] = rt[q].w;
        }
        __syncthreads();
        if (kc < Pd / 32 - 1) fetch(kc + 1);

#pragma unroll 8
        for (int k = 0; k < 32; k++) {
            float4 a0 = *(const float4*)&Ps[k][ty * 8];
            float4 a1 = *(const float4*)&Ps[k][ty * 8 + 4];
            ulonglong2 t0 = *(const ulonglong2*)&Ts[k][tx * 4];
            ull a2[8];
            a2[0] = pack2s(a0.x); a2[1] = pack2s(a0.y);
            a2[2] = pack2s(a0.z); a2[3] = pack2s(a0.w);
            a2[4] = pack2s(a1.x); a2[5] = pack2s(a1.y);
            a2[6] = pack2s(a1.z); a2[7] = pack2s(a1.w);
#pragma unroll
            for (int i = 0; i < 8; i++) {
                acc[i][0] = ffma2(a2[i], t0.x, acc[i][0]);
                acc[i][1] = ffma2(a2[i], t0.y, acc[i][1]);
            }
        }
    }

    // epilogue: scale by invn_t, mask by l < cnt, max over this thread's 4 cols
    float it[4]; int mk[4];
#pragma unroll
    for (int c = 0; c < 4; c++) {
        int l = l0 + tx * 4 + c;
        it[c] = g_invn_t[b * Lt + l];
        mk[c] = (l < cnt) ? 1 : 0;
    }
#pragma unroll
    for (int i = 0; i < 8; i++) {
        float v[4];
        unpack2(acc[i][0], v[0], v[1]);
        unpack2(acc[i][1], v[2], v[3]);
        float m = -3.4e38f;
#pragma unroll
        for (int c = 0; c < 4; c++) {
            float cand = mk[c] ? v[c] * it[c] : -3.4e38f;
            m = fmaxf(m, cand);
        }
        red[ty * 8 + i][tx] = m;
    }
    __syncthreads();
    if (tid < 128) {
        float m = red[tid][0];
#pragma unroll
        for (int x = 1; x < 16; x++) m = fmaxf(m, red[tid][x]);
        int gn = m0 + tid;
        if (gn < Np)
            g_part[((size_t)b * 4 + lblk) * Np + gn] = m;
    }
}

// ---------------------------------------------------------------------------
// K5: per-batch exact top-98 by rank counting (tie-break: lower index wins)
// ---------------------------------------------------------------------------
__global__ __launch_bounds__(256) void topk_kernel()
{
    const int b = blockIdx.x;
    const int tid = threadIdx.x;
    __shared__ float s[Np];
    __shared__ int sel[Np];

    if (tid < Np) {
        float m = g_part[((size_t)b * 4 + 0) * Np + tid];
        m = fmaxf(m, g_part[((size_t)b * 4 + 1) * Np + tid]);
        m = fmaxf(m, g_part[((size_t)b * 4 + 2) * Np + tid]);
        m = fmaxf(m, g_part[((size_t)b * 4 + 3) * Np + tid]);
        s[tid] = m * g_invn_p[b * Np + tid];
    }
    __syncthreads();
    if (tid < Np) {
        const float v = s[tid];
        int cnt = 0;
        for (int m = 0; m < Np; m++) {
            float sm = s[m];
            cnt += (sm > v) || (sm == v && m < tid);
        }
        sel[tid] = (cnt < Kt) ? 1 : 0;
    }
    __syncthreads();
    if (tid == 0) {
        const int base = b * OutRows;
        g_rowsrc[base] = b * (Np + 1);          // CLS row
        int pos = 1;
        for (int n = 0; n < Np; n++)
            if (sel[n]) g_rowsrc[base + pos++] = b * (Np + 1) + 1 + n;
    }
}

// ---------------------------------------------------------------------------
// K6: gather rows of state_at_drop into output (bit-exact copies)
// ---------------------------------------------------------------------------
__global__ __launch_bounds__(192) void gather_kernel(const float* __restrict__ state,
                                                     float* __restrict__ out)
{
    const int row = blockIdx.x;                 // 0 .. B*99-1
    const int src = g_rowsrc[row];
    const float4* sp = (const float4*)(state + (size_t)src * Ed);
    float4* op = (float4*)(out + (size_t)row * Ed);
    op[threadIdx.x] = sp[threadIdx.x];          // 192 x float4 = 768 floats
}

// ---------------------------------------------------------------------------
// kernel_launch
// ---------------------------------------------------------------------------
extern "C" void kernel_launch(void* const* d_in, const int* in_sizes, int n_in,
                              void* d_out, int out_size)
{
    const float* patch = (const float*)d_in[0];  // (B, N, E)
    const float* state = (const float*)d_in[1];  // (B, N+1, E)
    const float* token = (const float*)d_in[2];  // (B, L, E)
    const float* W_pp  = (const float*)d_in[3];  // (E, P)
    const float* b_pp  = (const float*)d_in[4];  // (P,)
    const float* W_tp  = (const float*)d_in[5];  // (E, P)
    const float* b_tp  = (const float*)d_in[6];  // (P,)
    const int*   attn  = (const int*)d_in[7];    // (B, L)
    float* out = (float*)d_out;

    void *pf_p, *tf_p, *ssp_p, *sst_p;
    cudaGetSymbolAddress(&pf_p, g_pf);
    cudaGetSymbolAddress(&tf_p, g_tf);
    cudaGetSymbolAddress(&ssp_p, g_ssp);
    cudaGetSymbolAddress(&sst_p, g_sst);

    compact_tokens<<<Bb, 256>>>(attn);
    gemm_proj<<<dim3(Pd / 128, (Bb * Np) / 128), 256>>>(
        patch, W_pp, b_pp, (float*)pf_p, (float*)ssp_p);
    gemm_proj_gather<<<dim3(Pd / 128, (Bb * Lt) / 128), 256>>>(
        token, W_tp, b_tp, (float*)tf_p, (float*)sst_p);
    rn_finish<<<(Bb * Np + Bb * Lt + 255) / 256, 256>>>();
    simmax<<<dim3(4, 2, Bb), 256>>>();
    topk_kernel<<<Bb, 256>>>();
    gather_kernel<<<Bb * OutRows, 192>>>(state, out);
}